// round 10
// baseline (speedup 1.0000x reference)
#include <cuda_runtime.h>
#include <math.h>
#include <float.h>

// ICP, fully persistent single kernel.
//   build uniform grid over B (count/scan/scatter, 4 grid barriers) ->
//   20 gated iterations: 4-concurrent-queries-per-warp grid 1-NN,
//     block reduce -> g_part, tree barrier, then EVERY block redundantly
//     grid-sums and solves Kabsch (block-local done/apply/T state) ->
//   final best-fit by last-arriving block.

#define NPTS 8192
#define MAX_ITERS 20
#define NB   256
#define TPB  256
#define G    48
#define G3   (G*G*G)
#define CPAD 131072               // padded cells (2 per thread)
#define GLO  (-6.0f)
#define GH   (0.25f)
#define GINVH (4.0f)
#define NBAR 25                   // 0..3 build, 4..23 iters, 24 final
#define FULLM 0xffffffffu

__device__ float4 g_src4[NPTS];
__device__ float4 g_B4[NPTS];
__device__ float4 g_cellPts[NPTS];        // grid-sorted B, w = index bits
__device__ int    g_cellCnt[CPAD];        // counts, then scatter cursors
__device__ int2   g_cellSC[CPAD];         // (start, count)
__device__ int    g_bsum[NB];
__device__ double g_part[NB][16];
__device__ int    g_sub[NBAR][16];        // arrival tree leaves
__device__ int    g_root[NBAR];           // arrival tree root
__device__ volatile int g_flag[NBAR];     // release flags (load-polled)

// ---------------------------------------------------------------------------
__device__ void kabsch3(const float H[9], const float cA[3], const float cB[3],
                        float R[9], float t[3]) {
    float K[3][3], V[3][3];
    #pragma unroll
    for (int i = 0; i < 3; ++i)
        #pragma unroll
        for (int j = 0; j < 3; ++j) {
            K[i][j] = H[0+i]*H[0+j] + H[3+i]*H[3+j] + H[6+i]*H[6+j];
            V[i][j] = (i == j) ? 1.0f : 0.0f;
        }
    const int pq[3][2] = {{0,1},{0,2},{1,2}};
    for (int sw = 0; sw < 8; ++sw) {
        for (int r3 = 0; r3 < 3; ++r3) {
            int p = pq[r3][0], q = pq[r3][1];
            float apq = K[p][q];
            if (fabsf(apq) < 1e-25f) continue;
            float theta = (K[q][q] - K[p][p]) / (2.0f * apq);
            float tt = 1.0f / (fabsf(theta) + sqrtf(theta*theta + 1.0f));
            if (theta < 0.0f) tt = -tt;
            float c = rsqrtf(tt*tt + 1.0f);
            float s = tt * c;
            #pragma unroll
            for (int r = 0; r < 3; ++r) {
                float kp = K[r][p], kq = K[r][q];
                K[r][p] = c*kp - s*kq; K[r][q] = s*kp + c*kq;
            }
            #pragma unroll
            for (int cc = 0; cc < 3; ++cc) {
                float kp = K[p][cc], kq = K[q][cc];
                K[p][cc] = c*kp - s*kq; K[q][cc] = s*kp + c*kq;
            }
            #pragma unroll
            for (int r = 0; r < 3; ++r) {
                float vp = V[r][p], vq = V[r][q];
                V[r][p] = c*vp - s*vq; V[r][q] = s*vp + c*vq;
            }
        }
    }
    float lam[3] = {K[0][0], K[1][1], K[2][2]};
    int ord[3] = {0, 1, 2};
    #pragma unroll
    for (int a = 0; a < 2; ++a)
        #pragma unroll
        for (int b = 0; b < 2 - a; ++b)
            if (lam[ord[b]] < lam[ord[b+1]]) { int tmp = ord[b]; ord[b] = ord[b+1]; ord[b+1] = tmp; }
    float Vs[3][3];
    #pragma unroll
    for (int k = 0; k < 3; ++k)
        #pragma unroll
        for (int r = 0; r < 3; ++r) Vs[r][k] = V[r][ord[k]];

    float U[3][3], sig[3];
    #pragma unroll
    for (int k = 0; k < 3; ++k) {
        float u0 = H[0]*Vs[0][k] + H[1]*Vs[1][k] + H[2]*Vs[2][k];
        float u1 = H[3]*Vs[0][k] + H[4]*Vs[1][k] + H[5]*Vs[2][k];
        float u2 = H[6]*Vs[0][k] + H[7]*Vs[1][k] + H[8]*Vs[2][k];
        float n = sqrtf(u0*u0 + u1*u1 + u2*u2);
        sig[k] = n;
        float inv = (n > 1e-25f) ? 1.0f / n : 0.0f;
        U[0][k] = u0*inv; U[1][k] = u1*inv; U[2][k] = u2*inv;
    }
    if (sig[2] <= 1e-10f * sig[0]) {
        float u0 = U[1][0]*U[2][1] - U[2][0]*U[1][1];
        float u1 = U[2][0]*U[0][1] - U[0][0]*U[2][1];
        float u2 = U[0][0]*U[1][1] - U[1][0]*U[0][1];
        float n = rsqrtf(fmaxf(u0*u0 + u1*u1 + u2*u2, 1e-30f));
        U[0][2] = u0*n; U[1][2] = u1*n; U[2][2] = u2*n;
    }
    float R0[3][3];
    #pragma unroll
    for (int i = 0; i < 3; ++i)
        #pragma unroll
        for (int j = 0; j < 3; ++j)
            R0[i][j] = Vs[i][0]*U[j][0] + Vs[i][1]*U[j][1] + Vs[i][2]*U[j][2];
    float det = R0[0][0]*(R0[1][1]*R0[2][2] - R0[1][2]*R0[2][1])
              - R0[0][1]*(R0[1][0]*R0[2][2] - R0[1][2]*R0[2][0])
              + R0[0][2]*(R0[1][0]*R0[2][1] - R0[1][1]*R0[2][0]);
    if (det < 0.0f) {
        #pragma unroll
        for (int i = 0; i < 3; ++i) Vs[i][2] = -Vs[i][2];
        #pragma unroll
        for (int i = 0; i < 3; ++i)
            #pragma unroll
            for (int j = 0; j < 3; ++j)
                R0[i][j] = Vs[i][0]*U[j][0] + Vs[i][1]*U[j][1] + Vs[i][2]*U[j][2];
    }
    #pragma unroll
    for (int i = 0; i < 3; ++i) {
        #pragma unroll
        for (int j = 0; j < 3; ++j) R[i*3+j] = R0[i][j];
        t[i] = cB[i] - (R0[i][0]*cA[0] + R0[i][1]*cA[1] + R0[i][2]*cA[2]);
    }
}

// ---------------------------------------------------------------------------
__device__ __forceinline__ void block_reduce16(double v[16], double sm[8][16],
                                               int tid, int bid) {
    #pragma unroll
    for (int q = 0; q < 16; ++q) {
        #pragma unroll
        for (int off = 16; off > 0; off >>= 1)
            v[q] += __shfl_down_sync(FULLM, v[q], off);
    }
    int warp = tid >> 5, lane = tid & 31;
    if (lane == 0) {
        #pragma unroll
        for (int q = 0; q < 16; ++q) sm[warp][q] = v[q];
    }
    __syncthreads();
    if (tid < 16) {
        double acc = 0.0;
        #pragma unroll
        for (int w = 0; w < 8; ++w) acc += sm[w][tid];
        g_part[bid][tid] = acc;
        __threadfence();
    }
    __syncthreads();
}

// every-block deterministic grid sum (identical order everywhere)
__device__ __forceinline__ void grid_sum16(double S[16], double sm[8][16], int tid) {
    double w[16];
    #pragma unroll
    for (int q = 0; q < 16; ++q) w[q] = g_part[tid][q];
    #pragma unroll
    for (int q = 0; q < 16; ++q) {
        #pragma unroll
        for (int off = 16; off > 0; off >>= 1)
            w[q] += __shfl_down_sync(FULLM, w[q], off);
    }
    int warp = tid >> 5, lane = tid & 31;
    __syncthreads();
    if (lane == 0) {
        #pragma unroll
        for (int q = 0; q < 16; ++q) sm[warp][q] = w[q];
    }
    __syncthreads();
    if (tid == 0) {
        #pragma unroll
        for (int q = 0; q < 16; ++q)
            S[q] = sm[0][q] + sm[1][q] + sm[2][q] + sm[3][q]
                 + sm[4][q] + sm[5][q] + sm[6][q] + sm[7][q];
    }
}

// tree arrival + flag release; returns last-arriver (uniform per block)
__device__ __forceinline__ bool gbar_arrive(int slot, int tid, int bid, int* sh) {
    __syncthreads();
    if (tid == 0) {
        __threadfence();
        int last = 0;
        if (atomicAdd(&g_sub[slot][bid & 15], 1) == 15)
            if (atomicAdd(&g_root[slot], 1) == 15)
                last = 1;
        *sh = last;
    }
    __syncthreads();
    return *sh != 0;
}
__device__ __forceinline__ void gbar(int slot, int tid, int bid, int* sh) {
    bool last = gbar_arrive(slot, tid, bid, sh);
    if (last && tid == 0) { __threadfence(); *(int*)&g_flag[slot] = 1; }
    if (tid == 0) {
        while (!g_flag[slot]) __nanosleep(16);
        __threadfence();
    }
    __syncthreads();
}

// ---------------------------------------------------------------------------
__global__ void __launch_bounds__(TPB, 2) k_icp(const float* __restrict__ A,
                                                const float* __restrict__ B,
                                                float* __restrict__ out) {
    __shared__ double sm[8][16];
    __shared__ int sscan[TPB];
    __shared__ int sbc, slast;
    __shared__ float sT[12];
    __shared__ float sprev;
    __shared__ int sdone, sapply;
    const int tid  = threadIdx.x;
    const int bid  = blockIdx.x;
    const int gt   = bid * TPB + tid;
    const int lane = tid & 31;
    const int warp = tid >> 5;
    const int seg  = lane >> 3;      // 4 query segments per warp
    const int sl   = lane & 7;

    if (tid == 0) { sdone = 0; sapply = 0; sprev = 0.f; }

    // ---- stage + count (fused; counts are zero: static init / end-of-run) ----
    int mycell = -1;
    if (gt < NPTS) {
        float ax = A[3*gt], ay = A[3*gt+1], az = A[3*gt+2];
        g_src4[gt] = make_float4(ax, ay, az, 0.f);
        float bx = B[3*gt], by = B[3*gt+1], bz = B[3*gt+2];
        g_B4[gt]   = make_float4(bx, by, bz, 0.f);
        int cx = min(max((int)floorf((bx - GLO) * GINVH), 0), G - 1);
        int cy = min(max((int)floorf((by - GLO) * GINVH), 0), G - 1);
        int cz = min(max((int)floorf((bz - GLO) * GINVH), 0), G - 1);
        mycell = (cz * G + cy) * G + cx;
        atomicAdd(&g_cellCnt[mycell], 1);
    }
    gbar(0, tid, bid, &slast);

    // ---- scan: per-thread 2 cells -> block scan -> block totals ----
    int t0 = gt * 2;
    int c0 = g_cellCnt[t0], c1 = g_cellCnt[t0 + 1];
    int s = c0 + c1;
    sscan[tid] = s;
    __syncthreads();
    for (int off = 1; off < TPB; off <<= 1) {
        int v = (tid >= off) ? sscan[tid - off] : 0;
        __syncthreads();
        sscan[tid] += v;
        __syncthreads();
    }
    int excl = sscan[tid] - s;
    if (tid == TPB - 1) g_bsum[bid] = sscan[TPB - 1];
    gbar(1, tid, bid, &slast);

    // ---- block offsets -> cellSC (start,count), zero cursors ----
    {
        int v = (tid < bid) ? g_bsum[tid] : 0;
        sscan[tid] = v;
        __syncthreads();
        for (int off = TPB / 2; off > 0; off >>= 1) {
            if (tid < off) sscan[tid] += sscan[tid + off];
            __syncthreads();
        }
        if (tid == 0) sbc = sscan[0];
        __syncthreads();
        int base = sbc + excl;
        g_cellSC[t0]     = make_int2(base, c0);
        g_cellSC[t0 + 1] = make_int2(base + c0, c1);
        g_cellCnt[t0] = 0;
        g_cellCnt[t0 + 1] = 0;
    }
    gbar(2, tid, bid, &slast);

    // ---- scatter ----
    if (gt < NPTS) {
        float4 b = g_B4[gt];
        int pos = g_cellSC[mycell].x + atomicAdd(&g_cellCnt[mycell], 1);
        g_cellPts[pos] = make_float4(b.x, b.y, b.z, __int_as_float(gt));
    }
    gbar(3, tid, bid, &slast);

    // ---- iteration loop ----
    const int wsrc = (bid * 8 + warp) * 4 + seg;   // this segment's query point
    for (int it = 0; it < MAX_ITERS; ++it) {
        if (sdone) break;

        // lazy-apply pending transform (all lanes of seg compute; sl==0 stores)
        float4 sp = g_src4[wsrc];
        float sx = sp.x, sy = sp.y, sz = sp.z;
        if (sapply) {
            float x = sT[0]*sx + sT[1]*sy + sT[2]*sz + sT[9];
            float y = sT[3]*sx + sT[4]*sy + sT[5]*sz + sT[10];
            float z = sT[6]*sx + sT[7]*sy + sT[8]*sz + sT[11];
            sx = x; sy = y; sz = z;
            if (sl == 0) g_src4[wsrc] = make_float4(sx, sy, sz, 0.f);
        }

        // ---- 4 concurrent NN queries per warp (8 lanes per query) ----
        int cx = min(max((int)floorf((sx - GLO) * GINVH), 0), G - 1);
        int cy = min(max((int)floorf((sy - GLO) * GINVH), 0), G - 1);
        int cz = min(max((int)floorf((sz - GLO) * GINVH), 0), G - 1);
        int rmax = max(max(cx, G-1-cx), max(max(cy, G-1-cy), max(cz, G-1-cz)));

        float best = FLT_MAX;
        int   bj   = 0x7fffffff;
        int   r    = 1;
        bool  shell = false;
        bool  segdone = false;
        for (;;) {
            unsigned act = __ballot_sync(FULLM, !segdone);
            if (!act) break;
            if (!segdone) {
                int side = 2*r + 1;
                int nc = side * side * side;
                for (int idx = sl; idx < nc; idx += 8) {
                    int dz = idx / (side * side);
                    int rem = idx - dz * side * side;
                    int dy = rem / side;
                    int dx = rem - dy * side;
                    dx -= r; dy -= r; dz -= r;
                    if (shell && max(abs(dx), max(abs(dy), abs(dz))) < r) continue;
                    int x = cx + dx, y = cy + dy, z = cz + dz;
                    if (x < 0 || x >= G || y < 0 || y >= G || z < 0 || z >= G) continue;
                    int2 sc = g_cellSC[(z * G + y) * G + x];
                    int k1 = sc.x + sc.y;
                    for (int k = sc.x; k < k1; ++k) {
                        float4 b = g_cellPts[k];
                        float ddx = sx - b.x, ddy = sy - b.y, ddz = sz - b.z;
                        float d2 = ddx*ddx + ddy*ddy + ddz*ddz;
                        int j = __float_as_int(b.w);
                        if (d2 < best || (d2 == best && j < bj)) { best = d2; bj = j; }
                    }
                }
            }
            // segment lexicographic min (all lanes participate)
            #pragma unroll
            for (int off = 1; off < 8; off <<= 1) {
                float od = __shfl_xor_sync(FULLM, best, off);
                int   oj = __shfl_xor_sync(FULLM, bj,   off);
                if (od < best || (od == best && oj < bj)) { best = od; bj = oj; }
            }
            if (!segdone) {
                float m = FLT_MAX;
                if (cx - r > 0)     m = fminf(m, sx - (GLO + (cx - r) * GH));
                if (cx + r < G - 1) m = fminf(m, (GLO + (cx + r + 1) * GH) - sx);
                if (cy - r > 0)     m = fminf(m, sy - (GLO + (cy - r) * GH));
                if (cy + r < G - 1) m = fminf(m, (GLO + (cy + r + 1) * GH) - sy);
                if (cz - r > 0)     m = fminf(m, sz - (GLO + (cz - r) * GH));
                if (cz + r < G - 1) m = fminf(m, (GLO + (cz + r + 1) * GH) - sz);
                if (best <= m * m || r >= rmax) segdone = true;
                else { ++r; shell = true; }
            }
        }

        // accumulate per-point terms on segment leaders
        double acc[16];
        if (sl == 0) {
            float4 b = g_B4[bj];
            double dsx = sx, dsy = sy, dsz = sz;
            double dbx = b.x, dby = b.y, dbz = b.z;
            acc[0] = dsx;  acc[1] = dsy;  acc[2] = dsz;
            acc[3] = dbx;  acc[4] = dby;  acc[5] = dbz;
            acc[6]  = dsx*dbx; acc[7]  = dsx*dby; acc[8]  = dsx*dbz;
            acc[9]  = dsy*dbx; acc[10] = dsy*dby; acc[11] = dsy*dbz;
            acc[12] = dsz*dbx; acc[13] = dsz*dby; acc[14] = dsz*dbz;
            acc[15] = (double)sqrtf(fmaxf(best, 0.0f) + 1e-12f);
        } else {
            #pragma unroll
            for (int q = 0; q < 16; ++q) acc[q] = 0.0;
        }
        block_reduce16(acc, sm, tid, bid);

        // barrier, then EVERY block redundantly sums + solves (deterministic)
        gbar(4 + it, tid, bid, &slast);
        double S[16];
        grid_sum16(S, sm, tid);
        if (tid == 0) {
            const double N = (double)NPTS;
            double cAd[3] = {S[0]/N, S[1]/N, S[2]/N};
            double cBd[3] = {S[3]/N, S[4]/N, S[5]/N};
            float H[9], cA[3], cB[3];
            #pragma unroll
            for (int rr = 0; rr < 3; ++rr) {
                cA[rr] = (float)cAd[rr]; cB[rr] = (float)cBd[rr];
                #pragma unroll
                for (int cc = 0; cc < 3; ++cc)
                    H[rr*3+cc] = (float)(S[6 + 3*rr + cc]/N - cAd[rr]*cBd[cc]);
            }
            float R[9], t[3];
            kabsch3(H, cA, cB, R, t);
            #pragma unroll
            for (int q = 0; q < 9; ++q) sT[q] = R[q];
            sT[9] = t[0]; sT[10] = t[1]; sT[11] = t[2];
            float errf = (float)(S[15] / N);
            if (fabsf(sprev - errf) < 1e-3f) sdone = 1;
            sprev = errf;
            sapply = 1;
        }
        __syncthreads();
    }

    // ---- final best-fit A -> src (pending transform applied on read) ----
    double v[16];
    if (bid < NPTS / TPB) {
        int i2 = bid * TPB + tid;
        float4 sp = g_src4[i2];
        float sx = sp.x, sy = sp.y, sz = sp.z;
        if (sapply) {
            float x = sT[0]*sx + sT[1]*sy + sT[2]*sz + sT[9];
            float y = sT[3]*sx + sT[4]*sy + sT[5]*sz + sT[10];
            float z = sT[6]*sx + sT[7]*sy + sT[8]*sz + sT[11];
            sx = x; sy = y; sz = z;
        }
        float ax = A[3*i2], ay = A[3*i2+1], az = A[3*i2+2];
        double pax = ax, pay = ay, paz = az;
        double pbx = sx, pby = sy, pbz = sz;
        v[0] = pax; v[1] = pay; v[2] = paz;
        v[3] = pbx; v[4] = pby; v[5] = pbz;
        v[6]  = pax*pbx; v[7]  = pax*pby; v[8]  = pax*pbz;
        v[9]  = pay*pbx; v[10] = pay*pby; v[11] = pay*pbz;
        v[12] = paz*pbx; v[13] = paz*pby; v[14] = paz*pbz;
        v[15] = 0.0;
    } else {
        #pragma unroll
        for (int q = 0; q < 16; ++q) v[q] = 0.0;
    }
    block_reduce16(v, sm, tid, bid);

    // zero own cellCnt slice for the next graph replay (pre-arrive)
    g_cellCnt[gt] = 0;
    g_cellCnt[gt + 65536] = 0;

    bool last = gbar_arrive(NBAR - 1, tid, bid, &slast);
    if (!last) return;

    if (tid == 0) __threadfence();
    __syncthreads();
    double S[16];
    grid_sum16(S, sm, tid);
    if (tid == 0) {
        const double N = (double)NPTS;
        double cAd[3] = {S[0]/N, S[1]/N, S[2]/N};
        double cBd[3] = {S[3]/N, S[4]/N, S[5]/N};
        float H[9], cA[3], cB[3];
        #pragma unroll
        for (int rr = 0; rr < 3; ++rr) {
            cA[rr] = (float)cAd[rr]; cB[rr] = (float)cBd[rr];
            #pragma unroll
            for (int cc = 0; cc < 3; ++cc)
                H[rr*3+cc] = (float)(S[6 + 3*rr + cc]/N - cAd[rr]*cBd[cc]);
        }
        float R[9], t[3];
        kabsch3(H, cA, cB, R, t);
        #pragma unroll
        for (int rr = 0; rr < 3; ++rr) {
            out[rr*4+0] = R[rr*3+0]; out[rr*4+1] = R[rr*3+1];
            out[rr*4+2] = R[rr*3+2]; out[rr*4+3] = t[rr];
        }
        out[12] = 0.f; out[13] = 0.f; out[14] = 0.f; out[15] = 1.f;
    }
    // rearm barrier state (only this block is alive)
    __syncthreads();
    for (int k2 = tid; k2 < NBAR * 16; k2 += TPB) ((int*)g_sub)[k2] = 0;
    for (int k2 = tid; k2 < NBAR; k2 += TPB) { g_root[k2] = 0; *(int*)&g_flag[k2] = 0; }
}

// ---------------------------------------------------------------------------
extern "C" void kernel_launch(void* const* d_in, const int* in_sizes, int n_in,
                              void* d_out, int out_size) {
    const float* A = (const float*)d_in[0];
    const float* B = (const float*)d_in[1];
    float* out = (float*)d_out;
    k_icp<<<NB, TPB>>>(A, B, out);
}

// round 13
// speedup vs baseline: 2.0565x; 2.0565x over previous
#include <cuda_runtime.h>
#include <math.h>
#include <float.h>

// ICP, persistent single kernel.
// Build grid over B (4 threadfence barriers, one-time) ->
// 20 gated iterations: warp-per-query grid 1-NN (all grid data L1-resident;
//   NO fences in the loop), single-thread-owned .cg stores + release-arrive
//   for cross-block sums, last arriver solves Kabsch, .cg flag release ->
// final best-fit with warp-local ownership (no cross-SM plain reads).

#define NPTS 8192
#define MAX_ITERS 20
#define NB   256
#define TPB  256
#define G    48
#define G3   (G*G*G)
#define CPAD 131072
#define GLO  (-6.0f)
#define GH   (0.25f)
#define GINVH (4.0f)
#define NBAR 25                   // 0..3 build, 4..23 iters, 24 final
#define FULLM 0xffffffffu

__device__ float4 g_src4[NPTS];
__device__ float4 g_B4[NPTS];
__device__ float4 g_cellPts[NPTS];
__device__ int    g_cellCnt[CPAD];
__device__ int2   g_cellSC[CPAD];
__device__ int    g_bsum[NB];
__device__ double g_part[NB][16];         // stored ONLY by each block's tid0 (.cg)
__device__ float  g_T[12];                // solver tid0 .cg
__device__ int    g_done;
__device__ float  g_prev_err;
__device__ int    g_root[NBAR];
__device__ int    g_flag[NBAR];

// ---- scoped-atomic / cg helpers -------------------------------------------
__device__ __forceinline__ int atomAddRel(int* p, int v) {
    int o; asm volatile("atom.release.gpu.global.add.s32 %0,[%1],%2;"
                        : "=r"(o) : "l"(p), "r"(v) : "memory"); return o;
}
__device__ __forceinline__ void redRel(int* p, int v) {
    asm volatile("red.release.gpu.global.add.s32 [%0],%1;"
                 :: "l"(p), "r"(v) : "memory");
}
__device__ __forceinline__ int ldcg_i(const int* p) {
    int v; asm volatile("ld.global.cg.s32 %0,[%1];" : "=r"(v) : "l"(p) : "memory");
    return v;
}
__device__ __forceinline__ float ldcg_f(const float* p) {
    float v; asm volatile("ld.global.cg.f32 %0,[%1];" : "=f"(v) : "l"(p) : "memory");
    return v;
}
__device__ __forceinline__ double ldcg_d(const double* p) {
    double v; asm volatile("ld.global.cg.f64 %0,[%1];" : "=d"(v) : "l"(p) : "memory");
    return v;
}
__device__ __forceinline__ void stcg_i(int* p, int v) {
    asm volatile("st.global.cg.s32 [%0],%1;" :: "l"(p), "r"(v) : "memory");
}
__device__ __forceinline__ void stcg_f(float* p, float v) {
    asm volatile("st.global.cg.f32 [%0],%1;" :: "l"(p), "f"(v) : "memory");
}
__device__ __forceinline__ void stcg_d(double* p, double v) {
    asm volatile("st.global.cg.f64 [%0],%1;" :: "l"(p), "d"(v) : "memory");
}

// ---------------------------------------------------------------------------
__device__ void kabsch3(const float H[9], const float cA[3], const float cB[3],
                        float R[9], float t[3]) {
    float K[3][3], V[3][3];
    #pragma unroll
    for (int i = 0; i < 3; ++i)
        #pragma unroll
        for (int j = 0; j < 3; ++j) {
            K[i][j] = H[0+i]*H[0+j] + H[3+i]*H[3+j] + H[6+i]*H[6+j];
            V[i][j] = (i == j) ? 1.0f : 0.0f;
        }
    const int pq[3][2] = {{0,1},{0,2},{1,2}};
    for (int sw = 0; sw < 8; ++sw) {
        for (int r3 = 0; r3 < 3; ++r3) {
            int p = pq[r3][0], q = pq[r3][1];
            float apq = K[p][q];
            if (fabsf(apq) < 1e-25f) continue;
            float theta = (K[q][q] - K[p][p]) / (2.0f * apq);
            float tt = 1.0f / (fabsf(theta) + sqrtf(theta*theta + 1.0f));
            if (theta < 0.0f) tt = -tt;
            float c = rsqrtf(tt*tt + 1.0f);
            float s = tt * c;
            #pragma unroll
            for (int r = 0; r < 3; ++r) {
                float kp = K[r][p], kq = K[r][q];
                K[r][p] = c*kp - s*kq; K[r][q] = s*kp + c*kq;
            }
            #pragma unroll
            for (int cc = 0; cc < 3; ++cc) {
                float kp = K[p][cc], kq = K[q][cc];
                K[p][cc] = c*kp - s*kq; K[q][cc] = s*kp + c*kq;
            }
            #pragma unroll
            for (int r = 0; r < 3; ++r) {
                float vp = V[r][p], vq = V[r][q];
                V[r][p] = c*vp - s*vq; V[r][q] = s*vp + c*vq;
            }
        }
    }
    float lam[3] = {K[0][0], K[1][1], K[2][2]};
    int ord[3] = {0, 1, 2};
    #pragma unroll
    for (int a = 0; a < 2; ++a)
        #pragma unroll
        for (int b = 0; b < 2 - a; ++b)
            if (lam[ord[b]] < lam[ord[b+1]]) { int tmp = ord[b]; ord[b] = ord[b+1]; ord[b+1] = tmp; }
    float Vs[3][3];
    #pragma unroll
    for (int k = 0; k < 3; ++k)
        #pragma unroll
        for (int r = 0; r < 3; ++r) Vs[r][k] = V[r][ord[k]];

    float U[3][3], sig[3];
    #pragma unroll
    for (int k = 0; k < 3; ++k) {
        float u0 = H[0]*Vs[0][k] + H[1]*Vs[1][k] + H[2]*Vs[2][k];
        float u1 = H[3]*Vs[0][k] + H[4]*Vs[1][k] + H[5]*Vs[2][k];
        float u2 = H[6]*Vs[0][k] + H[7]*Vs[1][k] + H[8]*Vs[2][k];
        float n = sqrtf(u0*u0 + u1*u1 + u2*u2);
        sig[k] = n;
        float inv = (n > 1e-25f) ? 1.0f / n : 0.0f;
        U[0][k] = u0*inv; U[1][k] = u1*inv; U[2][k] = u2*inv;
    }
    if (sig[2] <= 1e-10f * sig[0]) {
        float u0 = U[1][0]*U[2][1] - U[2][0]*U[1][1];
        float u1 = U[2][0]*U[0][1] - U[0][0]*U[2][1];
        float u2 = U[0][0]*U[1][1] - U[1][0]*U[0][1];
        float n = rsqrtf(fmaxf(u0*u0 + u1*u1 + u2*u2, 1e-30f));
        U[0][2] = u0*n; U[1][2] = u1*n; U[2][2] = u2*n;
    }
    float R0[3][3];
    #pragma unroll
    for (int i = 0; i < 3; ++i)
        #pragma unroll
        for (int j = 0; j < 3; ++j)
            R0[i][j] = Vs[i][0]*U[j][0] + Vs[i][1]*U[j][1] + Vs[i][2]*U[j][2];
    float det = R0[0][0]*(R0[1][1]*R0[2][2] - R0[1][2]*R0[2][1])
              - R0[0][1]*(R0[1][0]*R0[2][2] - R0[1][2]*R0[2][0])
              + R0[0][2]*(R0[1][0]*R0[2][1] - R0[1][1]*R0[2][0]);
    if (det < 0.0f) {
        #pragma unroll
        for (int i = 0; i < 3; ++i) Vs[i][2] = -Vs[i][2];
        #pragma unroll
        for (int i = 0; i < 3; ++i)
            #pragma unroll
            for (int j = 0; j < 3; ++j)
                R0[i][j] = Vs[i][0]*U[j][0] + Vs[i][1]*U[j][1] + Vs[i][2]*U[j][2];
    }
    #pragma unroll
    for (int i = 0; i < 3; ++i) {
        #pragma unroll
        for (int j = 0; j < 3; ++j) R[i*3+j] = R0[i][j];
        t[i] = cB[i] - (R0[i][0]*cA[0] + R0[i][1]*cA[1] + R0[i][2]*cA[2]);
    }
}

// ---------------------------------------------------------------------------
// block reduce -> 16 sums left in sm[0][0..15] (shared)
__device__ __forceinline__ void block_reduce16_sh(double v[16], double sm[8][16],
                                                  int tid) {
    #pragma unroll
    for (int q = 0; q < 16; ++q) {
        #pragma unroll
        for (int off = 16; off > 0; off >>= 1)
            v[q] += __shfl_down_sync(FULLM, v[q], off);
    }
    int warp = tid >> 5, lane = tid & 31;
    if (lane == 0) {
        #pragma unroll
        for (int q = 0; q < 16; ++q) sm[warp][q] = v[q];
    }
    __syncthreads();
    if (tid < 16) {
        double acc = sm[0][tid];
        #pragma unroll
        for (int w = 1; w < 8; ++w) acc += sm[w][tid];
        sm[0][tid] = acc;
    }
    __syncthreads();
}

// solver-side deterministic grid sum via .cg loads
__device__ __forceinline__ void grid_sum16(double S[16], double sm[8][16], int tid) {
    double w[16];
    #pragma unroll
    for (int q = 0; q < 16; ++q) w[q] = ldcg_d(&g_part[tid][q]);
    #pragma unroll
    for (int q = 0; q < 16; ++q) {
        #pragma unroll
        for (int off = 16; off > 0; off >>= 1)
            w[q] += __shfl_down_sync(FULLM, w[q], off);
    }
    int warp = tid >> 5, lane = tid & 31;
    __syncthreads();
    if (lane == 0) {
        #pragma unroll
        for (int q = 0; q < 16; ++q) sm[warp][q] = w[q];
    }
    __syncthreads();
    if (tid == 0) {
        #pragma unroll
        for (int q = 0; q < 16; ++q)
            S[q] = sm[0][q] + sm[1][q] + sm[2][q] + sm[3][q]
                 + sm[4][q] + sm[5][q] + sm[6][q] + sm[7][q];
    }
}

// build-phase barrier (threadfence; empirically validated in R8-R10)
__device__ __forceinline__ void gbarF(int slot, int tid) {
    __syncthreads();
    if (tid == 0) {
        __threadfence();
        if (atomicAdd(&g_root[slot], 1) == NB - 1) { __threadfence(); g_flag[slot] = 1; }
        while (ldcg_i(&g_flag[slot]) == 0) __nanosleep(32);
        __threadfence();
    }
    __syncthreads();
}

// ---------------------------------------------------------------------------
// warp-cooperative exact 1-NN via expanding Chebyshev rings
__device__ __forceinline__ void nn_query(float sx, float sy, float sz,
                                         int lane, float& best_out, int& bj_out) {
    int cx = min(max((int)floorf((sx - GLO) * GINVH), 0), G - 1);
    int cy = min(max((int)floorf((sy - GLO) * GINVH), 0), G - 1);
    int cz = min(max((int)floorf((sz - GLO) * GINVH), 0), G - 1);
    int rmax = max(max(cx, G-1-cx), max(max(cy, G-1-cy), max(cz, G-1-cz)));

    float best = FLT_MAX;
    int   bj   = 0x7fffffff;
    int   r    = 1;
    bool  shell = false;
    for (;;) {
        int side = 2*r + 1;
        int nc = side * side * side;
        for (int idx = lane; idx < nc; idx += 32) {
            int dz = idx / (side * side);
            int rem = idx - dz * side * side;
            int dy = rem / side;
            int dx = rem - dy * side;
            dx -= r; dy -= r; dz -= r;
            if (shell && max(abs(dx), max(abs(dy), abs(dz))) < r) continue;
            int x = cx + dx, y = cy + dy, z = cz + dz;
            if (x < 0 || x >= G || y < 0 || y >= G || z < 0 || z >= G) continue;
            int2 sc = g_cellSC[(z * G + y) * G + x];
            int k1 = sc.x + sc.y;
            for (int k = sc.x; k < k1; ++k) {
                float4 b = g_cellPts[k];
                float ddx = sx - b.x, ddy = sy - b.y, ddz = sz - b.z;
                float d2 = ddx*ddx + ddy*ddy + ddz*ddz;
                int j = __float_as_int(b.w);
                if (d2 < best || (d2 == best && j < bj)) { best = d2; bj = j; }
            }
        }
        #pragma unroll
        for (int off = 16; off > 0; off >>= 1) {
            float od = __shfl_xor_sync(FULLM, best, off);
            int   oj = __shfl_xor_sync(FULLM, bj,   off);
            if (od < best || (od == best && oj < bj)) { best = od; bj = oj; }
        }
        float m = FLT_MAX;
        if (cx - r > 0)     m = fminf(m, sx - (GLO + (cx - r) * GH));
        if (cx + r < G - 1) m = fminf(m, (GLO + (cx + r + 1) * GH) - sx);
        if (cy - r > 0)     m = fminf(m, sy - (GLO + (cy - r) * GH));
        if (cy + r < G - 1) m = fminf(m, (GLO + (cy + r + 1) * GH) - sy);
        if (cz - r > 0)     m = fminf(m, sz - (GLO + (cz - r) * GH));
        if (cz + r < G - 1) m = fminf(m, (GLO + (cz + r + 1) * GH) - sz);
        if (best <= m * m) break;
        if (r >= rmax) break;
        ++r;
        shell = true;
    }
    best_out = best;
    bj_out = bj;
}

// store block partials (tid0 only) + release-arrive; returns last-arriver flag
__device__ __forceinline__ bool store_and_arrive(int slot, int tid,
                                                 double sm[8][16], int* sh, int bid) {
    if (tid == 0) {
        #pragma unroll
        for (int q = 0; q < 16; ++q) stcg_d(&g_part[bid][q], sm[0][q]);
        *sh = (atomAddRel(&g_root[slot], 1) == NB - 1);
    }
    __syncthreads();
    return *sh != 0;
}

// ---------------------------------------------------------------------------
__global__ void __launch_bounds__(TPB, 2) k_icp(const float* __restrict__ A,
                                                const float* __restrict__ B,
                                                float* __restrict__ out) {
    __shared__ double sm[8][16];
    __shared__ int sscan[TPB];
    __shared__ int sbc, slast, sdone;
    __shared__ float sT[12];
    const int tid  = threadIdx.x;
    const int bid  = blockIdx.x;
    const int gt   = bid * TPB + tid;
    const int lane = tid & 31;
    const int warp = tid >> 5;

    // ---- stage + count ----
    int mycell = -1;
    if (gt < NPTS) {
        float ax = A[3*gt], ay = A[3*gt+1], az = A[3*gt+2];
        g_src4[gt] = make_float4(ax, ay, az, 0.f);
        float bx = B[3*gt], by = B[3*gt+1], bz = B[3*gt+2];
        g_B4[gt]   = make_float4(bx, by, bz, 0.f);
        int cx = min(max((int)floorf((bx - GLO) * GINVH), 0), G - 1);
        int cy = min(max((int)floorf((by - GLO) * GINVH), 0), G - 1);
        int cz = min(max((int)floorf((bz - GLO) * GINVH), 0), G - 1);
        mycell = (cz * G + cy) * G + cx;
        atomicAdd(&g_cellCnt[mycell], 1);
    }
    gbarF(0, tid);

    // ---- scan ----
    int t0 = gt * 2;
    int c0 = g_cellCnt[t0], c1 = g_cellCnt[t0 + 1];
    int s = c0 + c1;
    sscan[tid] = s;
    __syncthreads();
    for (int off = 1; off < TPB; off <<= 1) {
        int v = (tid >= off) ? sscan[tid - off] : 0;
        __syncthreads();
        sscan[tid] += v;
        __syncthreads();
    }
    int excl = sscan[tid] - s;
    if (tid == TPB - 1) g_bsum[bid] = sscan[TPB - 1];
    gbarF(1, tid);

    // ---- block offsets -> cellSC, zero cursors ----
    {
        int v = (tid < bid) ? g_bsum[tid] : 0;
        sscan[tid] = v;
        __syncthreads();
        for (int off = TPB / 2; off > 0; off >>= 1) {
            if (tid < off) sscan[tid] += sscan[tid + off];
            __syncthreads();
        }
        if (tid == 0) sbc = sscan[0];
        __syncthreads();
        int base = sbc + excl;
        g_cellSC[t0]     = make_int2(base, c0);
        g_cellSC[t0 + 1] = make_int2(base + c0, c1);
        g_cellCnt[t0] = 0;
        g_cellCnt[t0 + 1] = 0;
    }
    gbarF(2, tid);

    // ---- scatter ----
    if (gt < NPTS) {
        float4 b = g_B4[gt];
        int pos = g_cellSC[mycell].x + atomicAdd(&g_cellCnt[mycell], 1);
        g_cellPts[pos] = make_float4(b.x, b.y, b.z, __int_as_float(gt));
    }
    gbarF(3, tid);

    // ---- iteration loop (fence-free) ----
    bool pend = false;
    for (int it = 0; it < MAX_ITERS; ++it) {
        double acc[16];
        #pragma unroll
        for (int q = 0; q < 16; ++q) acc[q] = 0.0;

        #pragma unroll 1
        for (int sidx = 0; sidx < 4; ++sidx) {
            int wsrc = (bid * 8 + warp) * 4 + sidx;
            float4 sp = g_src4[wsrc];              // warp-owned: L1-coherent
            float sx = sp.x, sy = sp.y, sz = sp.z;
            if (pend) {
                float x = sT[0]*sx + sT[1]*sy + sT[2]*sz + sT[9];
                float y = sT[3]*sx + sT[4]*sy + sT[5]*sz + sT[10];
                float z = sT[6]*sx + sT[7]*sy + sT[8]*sz + sT[11];
                sx = x; sy = y; sz = z;
                if (lane == 0) g_src4[wsrc] = make_float4(sx, sy, sz, 0.f);
            }
            float best; int bj;
            nn_query(sx, sy, sz, lane, best, bj);
            if (lane == 0) {
                float4 b = g_B4[bj];
                double dsx = sx, dsy = sy, dsz = sz;
                double dbx = b.x, dby = b.y, dbz = b.z;
                acc[0] += dsx;  acc[1] += dsy;  acc[2] += dsz;
                acc[3] += dbx;  acc[4] += dby;  acc[5] += dbz;
                acc[6]  += dsx*dbx; acc[7]  += dsx*dby; acc[8]  += dsx*dbz;
                acc[9]  += dsy*dbx; acc[10] += dsy*dby; acc[11] += dsy*dbz;
                acc[12] += dsz*dbx; acc[13] += dsz*dby; acc[14] += dsz*dbz;
                acc[15] += (double)sqrtf(fmaxf(best, 0.0f) + 1e-12f);
            }
        }
        block_reduce16_sh(acc, sm, tid);

        int slot = 4 + it;
        bool last = store_and_arrive(slot, tid, sm, &slast, bid);
        if (last) {
            double S[16];
            grid_sum16(S, sm, tid);
            if (tid == 0) {
                const double N = (double)NPTS;
                double cAd[3] = {S[0]/N, S[1]/N, S[2]/N};
                double cBd[3] = {S[3]/N, S[4]/N, S[5]/N};
                float H[9], cA[3], cB[3];
                #pragma unroll
                for (int rr = 0; rr < 3; ++rr) {
                    cA[rr] = (float)cAd[rr]; cB[rr] = (float)cBd[rr];
                    #pragma unroll
                    for (int cc = 0; cc < 3; ++cc)
                        H[rr*3+cc] = (float)(S[6 + 3*rr + cc]/N - cAd[rr]*cBd[cc]);
                }
                float R[9], t[3];
                kabsch3(H, cA, cB, R, t);
                #pragma unroll
                for (int q = 0; q < 9; ++q) stcg_f(&g_T[q], R[q]);
                stcg_f(&g_T[9], t[0]); stcg_f(&g_T[10], t[1]); stcg_f(&g_T[11], t[2]);
                float errf = (float)(S[15] / N);
                float perr = ldcg_f(&g_prev_err);
                if (fabsf(perr - errf) < 1e-3f) stcg_i(&g_done, 1);
                stcg_f(&g_prev_err, errf);
                redRel(&g_flag[slot], 1);     // release: T/done ordered before
            }
        }
        if (tid == 0) { while (ldcg_i(&g_flag[slot]) == 0) __nanosleep(32); }
        __syncthreads();
        if (tid < 12) sT[tid] = ldcg_f(&g_T[tid]);
        if (tid == 12) sdone = ldcg_i(&g_done);
        __syncthreads();
        pend = true;
        if (sdone) break;
    }

    // ---- final best-fit A -> src, warp-local ownership ----
    double v[16];
    #pragma unroll
    for (int q = 0; q < 16; ++q) v[q] = 0.0;
    if (lane == 0) {
        #pragma unroll 1
        for (int sidx = 0; sidx < 4; ++sidx) {
            int wsrc = (bid * 8 + warp) * 4 + sidx;
            float4 sp = g_src4[wsrc];              // own warp's data, L1-coherent
            float sx = sp.x, sy = sp.y, sz = sp.z;
            if (pend) {
                float x = sT[0]*sx + sT[1]*sy + sT[2]*sz + sT[9];
                float y = sT[3]*sx + sT[4]*sy + sT[5]*sz + sT[10];
                float z = sT[6]*sx + sT[7]*sy + sT[8]*sz + sT[11];
                sx = x; sy = y; sz = z;
            }
            float ax = A[3*wsrc], ay = A[3*wsrc+1], az = A[3*wsrc+2];
            double pax = ax, pay = ay, paz = az;   // first arg  = A
            double pbx = sx, pby = sy, pbz = sz;   // second arg = src
            v[0] += pax; v[1] += pay; v[2] += paz;
            v[3] += pbx; v[4] += pby; v[5] += pbz;
            v[6]  += pax*pbx; v[7]  += pax*pby; v[8]  += pax*pbz;
            v[9]  += pay*pbx; v[10] += pay*pby; v[11] += pay*pbz;
            v[12] += paz*pbx; v[13] += paz*pby; v[14] += paz*pbz;
        }
        v[15] = 0.0;
    }
    block_reduce16_sh(v, sm, tid);

    // zero own cellCnt slice for next graph replay (before final arrive)
    g_cellCnt[gt] = 0;
    g_cellCnt[gt + 65536] = 0;

    bool last = store_and_arrive(NBAR - 1, tid, sm, &slast, bid);
    if (!last) return;

    double S[16];
    grid_sum16(S, sm, tid);
    if (tid == 0) {
        const double N = (double)NPTS;
        double cAd[3] = {S[0]/N, S[1]/N, S[2]/N};
        double cBd[3] = {S[3]/N, S[4]/N, S[5]/N};
        float H[9], cA[3], cB[3];
        #pragma unroll
        for (int rr = 0; rr < 3; ++rr) {
            cA[rr] = (float)cAd[rr]; cB[rr] = (float)cBd[rr];
            #pragma unroll
            for (int cc = 0; cc < 3; ++cc)
                H[rr*3+cc] = (float)(S[6 + 3*rr + cc]/N - cAd[rr]*cBd[cc]);
        }
        float R[9], t[3];
        kabsch3(H, cA, cB, R, t);
        #pragma unroll
        for (int rr = 0; rr < 3; ++rr) {
            out[rr*4+0] = R[rr*3+0]; out[rr*4+1] = R[rr*3+1];
            out[rr*4+2] = R[rr*3+2]; out[rr*4+3] = t[rr];
        }
        out[12] = 0.f; out[13] = 0.f; out[14] = 0.f; out[15] = 1.f;
        stcg_i(&g_done, 0);
        stcg_f(&g_prev_err, 0.f);
    }
    // rearm barrier state (only this block alive)
    __syncthreads();
    for (int k2 = tid; k2 < NBAR; k2 += TPB) { g_root[k2] = 0; g_flag[k2] = 0; }
}

// ---------------------------------------------------------------------------
extern "C" void kernel_launch(void* const* d_in, const int* in_sizes, int n_in,
                              void* d_out, int out_size) {
    const float* A = (const float*)d_in[0];
    const float* B = (const float*)d_in[1];
    float* out = (float*)d_out;
    k_icp<<<NB, TPB>>>(A, B, out);
}

// round 14
// speedup vs baseline: 2.1763x; 1.0582x over previous
#include <cuda_runtime.h>
#include <math.h>
#include <float.h>

// ICP, persistent single kernel.
// Build grid over B (4 threadfence barriers, one-time) ->
// 20 gated iterations: warp-per-query grid 1-NN with __any_sync ring
//   termination + REDUX.SYNC final argmin (short dependent chains; no fences),
//   single-thread-owned .cg stores + release-arrive, last arriver solves ->
// final best-fit with warp-local ownership.

#define NPTS 8192
#define MAX_ITERS 20
#define NB   256
#define TPB  256
#define G    48
#define G3   (G*G*G)
#define CPAD 131072
#define GLO  (-6.0f)
#define GH   (0.25f)
#define GINVH (4.0f)
#define NBAR 25
#define FULLM 0xffffffffu

__device__ float4 g_src4[NPTS];
__device__ float4 g_B4[NPTS];
__device__ float4 g_cellPts[NPTS];
__device__ int    g_cellCnt[CPAD];
__device__ int2   g_cellSC[CPAD];
__device__ int    g_bsum[NB];
__device__ double g_part[NB][16];         // stored ONLY by each block's tid0 (.cg)
__device__ float  g_T[12];
__device__ int    g_done;
__device__ float  g_prev_err;
__device__ int    g_root[NBAR];
__device__ int    g_flag[NBAR];

// ---- scoped-atomic / cg helpers -------------------------------------------
__device__ __forceinline__ int atomAddRel(int* p, int v) {
    int o; asm volatile("atom.release.gpu.global.add.s32 %0,[%1],%2;"
                        : "=r"(o) : "l"(p), "r"(v) : "memory"); return o;
}
__device__ __forceinline__ void redRel(int* p, int v) {
    asm volatile("red.release.gpu.global.add.s32 [%0],%1;"
                 :: "l"(p), "r"(v) : "memory");
}
__device__ __forceinline__ int ldcg_i(const int* p) {
    int v; asm volatile("ld.global.cg.s32 %0,[%1];" : "=r"(v) : "l"(p) : "memory");
    return v;
}
__device__ __forceinline__ float ldcg_f(const float* p) {
    float v; asm volatile("ld.global.cg.f32 %0,[%1];" : "=f"(v) : "l"(p) : "memory");
    return v;
}
__device__ __forceinline__ double ldcg_d(const double* p) {
    double v; asm volatile("ld.global.cg.f64 %0,[%1];" : "=d"(v) : "l"(p) : "memory");
    return v;
}
__device__ __forceinline__ void stcg_i(int* p, int v) {
    asm volatile("st.global.cg.s32 [%0],%1;" :: "l"(p), "r"(v) : "memory");
}
__device__ __forceinline__ void stcg_f(float* p, float v) {
    asm volatile("st.global.cg.f32 [%0],%1;" :: "l"(p), "f"(v) : "memory");
}
__device__ __forceinline__ void stcg_d(double* p, double v) {
    asm volatile("st.global.cg.f64 [%0],%1;" :: "l"(p), "d"(v) : "memory");
}

// ---------------------------------------------------------------------------
__device__ void kabsch3(const float H[9], const float cA[3], const float cB[3],
                        float R[9], float t[3]) {
    float K[3][3], V[3][3];
    #pragma unroll
    for (int i = 0; i < 3; ++i)
        #pragma unroll
        for (int j = 0; j < 3; ++j) {
            K[i][j] = H[0+i]*H[0+j] + H[3+i]*H[3+j] + H[6+i]*H[6+j];
            V[i][j] = (i == j) ? 1.0f : 0.0f;
        }
    const int pq[3][2] = {{0,1},{0,2},{1,2}};
    for (int sw = 0; sw < 5; ++sw) {
        for (int r3 = 0; r3 < 3; ++r3) {
            int p = pq[r3][0], q = pq[r3][1];
            float apq = K[p][q];
            if (fabsf(apq) < 1e-25f) continue;
            float theta = (K[q][q] - K[p][p]) / (2.0f * apq);
            float tt = 1.0f / (fabsf(theta) + sqrtf(theta*theta + 1.0f));
            if (theta < 0.0f) tt = -tt;
            float c = rsqrtf(tt*tt + 1.0f);
            float s = tt * c;
            #pragma unroll
            for (int r = 0; r < 3; ++r) {
                float kp = K[r][p], kq = K[r][q];
                K[r][p] = c*kp - s*kq; K[r][q] = s*kp + c*kq;
            }
            #pragma unroll
            for (int cc = 0; cc < 3; ++cc) {
                float kp = K[p][cc], kq = K[q][cc];
                K[p][cc] = c*kp - s*kq; K[q][cc] = s*kp + c*kq;
            }
            #pragma unroll
            for (int r = 0; r < 3; ++r) {
                float vp = V[r][p], vq = V[r][q];
                V[r][p] = c*vp - s*vq; V[r][q] = s*vp + c*vq;
            }
        }
    }
    float lam[3] = {K[0][0], K[1][1], K[2][2]};
    int ord[3] = {0, 1, 2};
    #pragma unroll
    for (int a = 0; a < 2; ++a)
        #pragma unroll
        for (int b = 0; b < 2 - a; ++b)
            if (lam[ord[b]] < lam[ord[b+1]]) { int tmp = ord[b]; ord[b] = ord[b+1]; ord[b+1] = tmp; }
    float Vs[3][3];
    #pragma unroll
    for (int k = 0; k < 3; ++k)
        #pragma unroll
        for (int r = 0; r < 3; ++r) Vs[r][k] = V[r][ord[k]];

    float U[3][3], sig[3];
    #pragma unroll
    for (int k = 0; k < 3; ++k) {
        float u0 = H[0]*Vs[0][k] + H[1]*Vs[1][k] + H[2]*Vs[2][k];
        float u1 = H[3]*Vs[0][k] + H[4]*Vs[1][k] + H[5]*Vs[2][k];
        float u2 = H[6]*Vs[0][k] + H[7]*Vs[1][k] + H[8]*Vs[2][k];
        float n = sqrtf(u0*u0 + u1*u1 + u2*u2);
        sig[k] = n;
        float inv = (n > 1e-25f) ? 1.0f / n : 0.0f;
        U[0][k] = u0*inv; U[1][k] = u1*inv; U[2][k] = u2*inv;
    }
    if (sig[2] <= 1e-10f * sig[0]) {
        float u0 = U[1][0]*U[2][1] - U[2][0]*U[1][1];
        float u1 = U[2][0]*U[0][1] - U[0][0]*U[2][1];
        float u2 = U[0][0]*U[1][1] - U[1][0]*U[0][1];
        float n = rsqrtf(fmaxf(u0*u0 + u1*u1 + u2*u2, 1e-30f));
        U[0][2] = u0*n; U[1][2] = u1*n; U[2][2] = u2*n;
    }
    float R0[3][3];
    #pragma unroll
    for (int i = 0; i < 3; ++i)
        #pragma unroll
        for (int j = 0; j < 3; ++j)
            R0[i][j] = Vs[i][0]*U[j][0] + Vs[i][1]*U[j][1] + Vs[i][2]*U[j][2];
    float det = R0[0][0]*(R0[1][1]*R0[2][2] - R0[1][2]*R0[2][1])
              - R0[0][1]*(R0[1][0]*R0[2][2] - R0[1][2]*R0[2][0])
              + R0[0][2]*(R0[1][0]*R0[2][1] - R0[1][1]*R0[2][0]);
    if (det < 0.0f) {
        #pragma unroll
        for (int i = 0; i < 3; ++i) Vs[i][2] = -Vs[i][2];
        #pragma unroll
        for (int i = 0; i < 3; ++i)
            #pragma unroll
            for (int j = 0; j < 3; ++j)
                R0[i][j] = Vs[i][0]*U[j][0] + Vs[i][1]*U[j][1] + Vs[i][2]*U[j][2];
    }
    #pragma unroll
    for (int i = 0; i < 3; ++i) {
        #pragma unroll
        for (int j = 0; j < 3; ++j) R[i*3+j] = R0[i][j];
        t[i] = cB[i] - (R0[i][0]*cA[0] + R0[i][1]*cA[1] + R0[i][2]*cA[2]);
    }
}

// ---------------------------------------------------------------------------
__device__ __forceinline__ void block_reduce16_sh(double v[16], double sm[8][16],
                                                  int tid) {
    #pragma unroll
    for (int q = 0; q < 16; ++q) {
        #pragma unroll
        for (int off = 16; off > 0; off >>= 1)
            v[q] += __shfl_down_sync(FULLM, v[q], off);
    }
    int warp = tid >> 5, lane = tid & 31;
    if (lane == 0) {
        #pragma unroll
        for (int q = 0; q < 16; ++q) sm[warp][q] = v[q];
    }
    __syncthreads();
    if (tid < 16) {
        double acc = sm[0][tid];
        #pragma unroll
        for (int w = 1; w < 8; ++w) acc += sm[w][tid];
        sm[0][tid] = acc;
    }
    __syncthreads();
}

__device__ __forceinline__ void grid_sum16(double S[16], double sm[8][16], int tid) {
    double w[16];
    #pragma unroll
    for (int q = 0; q < 16; ++q) w[q] = ldcg_d(&g_part[tid][q]);
    #pragma unroll
    for (int q = 0; q < 16; ++q) {
        #pragma unroll
        for (int off = 16; off > 0; off >>= 1)
            w[q] += __shfl_down_sync(FULLM, w[q], off);
    }
    int warp = tid >> 5, lane = tid & 31;
    __syncthreads();
    if (lane == 0) {
        #pragma unroll
        for (int q = 0; q < 16; ++q) sm[warp][q] = w[q];
    }
    __syncthreads();
    if (tid == 0) {
        #pragma unroll
        for (int q = 0; q < 16; ++q)
            S[q] = sm[0][q] + sm[1][q] + sm[2][q] + sm[3][q]
                 + sm[4][q] + sm[5][q] + sm[6][q] + sm[7][q];
    }
}

// build-phase barrier (threadfence; one-time cost)
__device__ __forceinline__ void gbarF(int slot, int tid) {
    __syncthreads();
    if (tid == 0) {
        __threadfence();
        if (atomicAdd(&g_root[slot], 1) == NB - 1) { __threadfence(); g_flag[slot] = 1; }
        while (ldcg_i(&g_flag[slot]) == 0) __nanosleep(32);
        __threadfence();
    }
    __syncthreads();
}

// ---------------------------------------------------------------------------
// warp-cooperative exact 1-NN: lane-local bests, __any_sync ring termination,
// REDUX.SYNC final argmin (deterministic: min d2, then min index).
__device__ __forceinline__ void nn_query(float sx, float sy, float sz,
                                         int lane, float& best_out, int& bj_out) {
    int cx = min(max((int)floorf((sx - GLO) * GINVH), 0), G - 1);
    int cy = min(max((int)floorf((sy - GLO) * GINVH), 0), G - 1);
    int cz = min(max((int)floorf((sz - GLO) * GINVH), 0), G - 1);
    int rmax = max(max(cx, G-1-cx), max(max(cy, G-1-cy), max(cz, G-1-cz)));

    float best = FLT_MAX;
    int   bj   = 0x7fffffff;
    int   r    = 1;
    bool  shell = false;
    for (;;) {
        int side = 2*r + 1;
        int nc = side * side * side;
        for (int idx = lane; idx < nc; idx += 32) {
            int dz = idx / (side * side);
            int rem = idx - dz * side * side;
            int dy = rem / side;
            int dx = rem - dy * side;
            dx -= r; dy -= r; dz -= r;
            if (shell && max(abs(dx), max(abs(dy), abs(dz))) < r) continue;
            int x = cx + dx, y = cy + dy, z = cz + dz;
            if (x < 0 || x >= G || y < 0 || y >= G || z < 0 || z >= G) continue;
            int2 sc = g_cellSC[(z * G + y) * G + x];
            int k1 = sc.x + sc.y;
            for (int k = sc.x; k < k1; ++k) {
                float4 b = g_cellPts[k];
                float ddx = sx - b.x, ddy = sy - b.y, ddz = sz - b.z;
                float d2 = ddx*ddx + ddy*ddy + ddz*ddz;
                int j = __float_as_int(b.w);
                if (d2 < best || (d2 == best && j < bj)) { best = d2; bj = j; }
            }
        }
        // termination: warp-min(best) <= m^2  <=>  any lane best <= m^2
        float m = FLT_MAX;
        if (cx - r > 0)     m = fminf(m, sx - (GLO + (cx - r) * GH));
        if (cx + r < G - 1) m = fminf(m, (GLO + (cx + r + 1) * GH) - sx);
        if (cy - r > 0)     m = fminf(m, sy - (GLO + (cy - r) * GH));
        if (cy + r < G - 1) m = fminf(m, (GLO + (cy + r + 1) * GH) - sy);
        if (cz - r > 0)     m = fminf(m, sz - (GLO + (cz - r) * GH));
        if (cz + r < G - 1) m = fminf(m, (GLO + (cz + r + 1) * GH) - sz);
        if (__any_sync(FULLM, best <= m * m)) break;
        if (r >= rmax) break;
        ++r;
        shell = true;
    }
    // final argmin: d2 bits are order-preserving (non-negative floats)
    unsigned db = __float_as_uint(best);
    unsigned mn = __reduce_min_sync(FULLM, db);
    unsigned cbj = (db == mn) ? (unsigned)bj : 0xffffffffu;
    bj = (int)__reduce_min_sync(FULLM, cbj);
    best_out = __uint_as_float(mn);
    bj_out = bj;
}

// store block partials (tid0 only) + release-arrive
__device__ __forceinline__ bool store_and_arrive(int slot, int tid,
                                                 double sm[8][16], int* sh, int bid) {
    if (tid == 0) {
        #pragma unroll
        for (int q = 0; q < 16; ++q) stcg_d(&g_part[bid][q], sm[0][q]);
        *sh = (atomAddRel(&g_root[slot], 1) == NB - 1);
    }
    __syncthreads();
    return *sh != 0;
}

// ---------------------------------------------------------------------------
__global__ void __launch_bounds__(TPB, 2) k_icp(const float* __restrict__ A,
                                                const float* __restrict__ B,
                                                float* __restrict__ out) {
    __shared__ double sm[8][16];
    __shared__ int sscan[TPB];
    __shared__ int sbc, slast, sdone;
    __shared__ float sT[12];
    const int tid  = threadIdx.x;
    const int bid  = blockIdx.x;
    const int gt   = bid * TPB + tid;
    const int lane = tid & 31;
    const int warp = tid >> 5;

    // ---- stage + count ----
    int mycell = -1;
    if (gt < NPTS) {
        float ax = A[3*gt], ay = A[3*gt+1], az = A[3*gt+2];
        g_src4[gt] = make_float4(ax, ay, az, 0.f);
        float bx = B[3*gt], by = B[3*gt+1], bz = B[3*gt+2];
        g_B4[gt]   = make_float4(bx, by, bz, 0.f);
        int cx = min(max((int)floorf((bx - GLO) * GINVH), 0), G - 1);
        int cy = min(max((int)floorf((by - GLO) * GINVH), 0), G - 1);
        int cz = min(max((int)floorf((bz - GLO) * GINVH), 0), G - 1);
        mycell = (cz * G + cy) * G + cx;
        atomicAdd(&g_cellCnt[mycell], 1);
    }
    gbarF(0, tid);

    // ---- scan ----
    int t0 = gt * 2;
    int c0 = g_cellCnt[t0], c1 = g_cellCnt[t0 + 1];
    int s = c0 + c1;
    sscan[tid] = s;
    __syncthreads();
    for (int off = 1; off < TPB; off <<= 1) {
        int v = (tid >= off) ? sscan[tid - off] : 0;
        __syncthreads();
        sscan[tid] += v;
        __syncthreads();
    }
    int excl = sscan[tid] - s;
    if (tid == TPB - 1) g_bsum[bid] = sscan[TPB - 1];
    gbarF(1, tid);

    // ---- block offsets -> cellSC, zero cursors ----
    {
        int v = (tid < bid) ? g_bsum[tid] : 0;
        sscan[tid] = v;
        __syncthreads();
        for (int off = TPB / 2; off > 0; off >>= 1) {
            if (tid < off) sscan[tid] += sscan[tid + off];
            __syncthreads();
        }
        if (tid == 0) sbc = sscan[0];
        __syncthreads();
        int base = sbc + excl;
        g_cellSC[t0]     = make_int2(base, c0);
        g_cellSC[t0 + 1] = make_int2(base + c0, c1);
        g_cellCnt[t0] = 0;
        g_cellCnt[t0 + 1] = 0;
    }
    gbarF(2, tid);

    // ---- scatter ----
    if (gt < NPTS) {
        float4 b = g_B4[gt];
        int pos = g_cellSC[mycell].x + atomicAdd(&g_cellCnt[mycell], 1);
        g_cellPts[pos] = make_float4(b.x, b.y, b.z, __int_as_float(gt));
    }
    gbarF(3, tid);

    // ---- iteration loop (fence-free) ----
    bool pend = false;
    for (int it = 0; it < MAX_ITERS; ++it) {
        double acc[16];
        #pragma unroll
        for (int q = 0; q < 16; ++q) acc[q] = 0.0;

        #pragma unroll 1
        for (int sidx = 0; sidx < 4; ++sidx) {
            int wsrc = (bid * 8 + warp) * 4 + sidx;
            float4 sp = g_src4[wsrc];
            float sx = sp.x, sy = sp.y, sz = sp.z;
            if (pend) {
                float x = sT[0]*sx + sT[1]*sy + sT[2]*sz + sT[9];
                float y = sT[3]*sx + sT[4]*sy + sT[5]*sz + sT[10];
                float z = sT[6]*sx + sT[7]*sy + sT[8]*sz + sT[11];
                sx = x; sy = y; sz = z;
                if (lane == 0) g_src4[wsrc] = make_float4(sx, sy, sz, 0.f);
            }
            float best; int bj;
            nn_query(sx, sy, sz, lane, best, bj);
            if (lane == 0) {
                float4 b = g_B4[bj];
                double dsx = sx, dsy = sy, dsz = sz;
                double dbx = b.x, dby = b.y, dbz = b.z;
                acc[0] += dsx;  acc[1] += dsy;  acc[2] += dsz;
                acc[3] += dbx;  acc[4] += dby;  acc[5] += dbz;
                acc[6]  += dsx*dbx; acc[7]  += dsx*dby; acc[8]  += dsx*dbz;
                acc[9]  += dsy*dbx; acc[10] += dsy*dby; acc[11] += dsy*dbz;
                acc[12] += dsz*dbx; acc[13] += dsz*dby; acc[14] += dsz*dbz;
                acc[15] += (double)sqrtf(fmaxf(best, 0.0f) + 1e-12f);
            }
        }
        block_reduce16_sh(acc, sm, tid);

        int slot = 4 + it;
        bool last = store_and_arrive(slot, tid, sm, &slast, bid);
        if (last) {
            double S[16];
            grid_sum16(S, sm, tid);
            if (tid == 0) {
                const double N = (double)NPTS;
                double cAd[3] = {S[0]/N, S[1]/N, S[2]/N};
                double cBd[3] = {S[3]/N, S[4]/N, S[5]/N};
                float H[9], cA[3], cB[3];
                #pragma unroll
                for (int rr = 0; rr < 3; ++rr) {
                    cA[rr] = (float)cAd[rr]; cB[rr] = (float)cBd[rr];
                    #pragma unroll
                    for (int cc = 0; cc < 3; ++cc)
                        H[rr*3+cc] = (float)(S[6 + 3*rr + cc]/N - cAd[rr]*cBd[cc]);
                }
                float R[9], t[3];
                kabsch3(H, cA, cB, R, t);
                #pragma unroll
                for (int q = 0; q < 9; ++q) stcg_f(&g_T[q], R[q]);
                stcg_f(&g_T[9], t[0]); stcg_f(&g_T[10], t[1]); stcg_f(&g_T[11], t[2]);
                float errf = (float)(S[15] / N);
                float perr = ldcg_f(&g_prev_err);
                if (fabsf(perr - errf) < 1e-3f) stcg_i(&g_done, 1);
                stcg_f(&g_prev_err, errf);
                redRel(&g_flag[slot], 1);
            }
        }
        if (tid == 0) { while (ldcg_i(&g_flag[slot]) == 0) __nanosleep(32); }
        __syncthreads();
        if (tid < 12) sT[tid] = ldcg_f(&g_T[tid]);
        if (tid == 12) sdone = ldcg_i(&g_done);
        __syncthreads();
        pend = true;
        if (sdone) break;
    }

    // ---- final best-fit A -> src, warp-local ownership ----
    double v[16];
    #pragma unroll
    for (int q = 0; q < 16; ++q) v[q] = 0.0;
    if (lane == 0) {
        #pragma unroll 1
        for (int sidx = 0; sidx < 4; ++sidx) {
            int wsrc = (bid * 8 + warp) * 4 + sidx;
            float4 sp = g_src4[wsrc];
            float sx = sp.x, sy = sp.y, sz = sp.z;
            if (pend) {
                float x = sT[0]*sx + sT[1]*sy + sT[2]*sz + sT[9];
                float y = sT[3]*sx + sT[4]*sy + sT[5]*sz + sT[10];
                float z = sT[6]*sx + sT[7]*sy + sT[8]*sz + sT[11];
                sx = x; sy = y; sz = z;
            }
            float ax = A[3*wsrc], ay = A[3*wsrc+1], az = A[3*wsrc+2];
            double pax = ax, pay = ay, paz = az;
            double pbx = sx, pby = sy, pbz = sz;
            v[0] += pax; v[1] += pay; v[2] += paz;
            v[3] += pbx; v[4] += pby; v[5] += pbz;
            v[6]  += pax*pbx; v[7]  += pax*pby; v[8]  += pax*pbz;
            v[9]  += pay*pbx; v[10] += pay*pby; v[11] += pay*pbz;
            v[12] += paz*pbx; v[13] += paz*pby; v[14] += paz*pbz;
        }
        v[15] = 0.0;
    }
    block_reduce16_sh(v, sm, tid);

    // zero own cellCnt slice for next graph replay
    g_cellCnt[gt] = 0;
    g_cellCnt[gt + 65536] = 0;

    bool last = store_and_arrive(NBAR - 1, tid, sm, &slast, bid);
    if (!last) return;

    double S[16];
    grid_sum16(S, sm, tid);
    if (tid == 0) {
        const double N = (double)NPTS;
        double cAd[3] = {S[0]/N, S[1]/N, S[2]/N};
        double cBd[3] = {S[3]/N, S[4]/N, S[5]/N};
        float H[9], cA[3], cB[3];
        #pragma unroll
        for (int rr = 0; rr < 3; ++rr) {
            cA[rr] = (float)cAd[rr]; cB[rr] = (float)cBd[rr];
            #pragma unroll
            for (int cc = 0; cc < 3; ++cc)
                H[rr*3+cc] = (float)(S[6 + 3*rr + cc]/N - cAd[rr]*cBd[cc]);
        }
        float R[9], t[3];
        kabsch3(H, cA, cB, R, t);
        #pragma unroll
        for (int rr = 0; rr < 3; ++rr) {
            out[rr*4+0] = R[rr*3+0]; out[rr*4+1] = R[rr*3+1];
            out[rr*4+2] = R[rr*3+2]; out[rr*4+3] = t[rr];
        }
        out[12] = 0.f; out[13] = 0.f; out[14] = 0.f; out[15] = 1.f;
        stcg_i(&g_done, 0);
        stcg_f(&g_prev_err, 0.f);
    }
    __syncthreads();
    for (int k2 = tid; k2 < NBAR; k2 += TPB) { g_root[k2] = 0; g_flag[k2] = 0; }
}

// ---------------------------------------------------------------------------
extern "C" void kernel_launch(void* const* d_in, const int* in_sizes, int n_in,
                              void* d_out, int out_size) {
    const float* A = (const float*)d_in[0];
    const float* B = (const float*)d_in[1];
    float* out = (float*)d_out;
    k_icp<<<NB, TPB>>>(A, B, out);
}